// round 17
// baseline (speedup 1.0000x reference)
#include <cuda_runtime.h>
#include <cuda_bf16.h>
#include <cuda_fp16.h>
#include <cstdint>

// Problem constants
#define SEQ   4096
#define DMOD  512
#define NHEAD 8
#define DK    64
#define MTOT  8192   // B * S = 2 * 4096
#define PADW  72     // smem row stride in 16-bit units (144 B): conflict-free ldmatrix
#define QSCALE 0.18033688f  // 0.125 * log2(e): softmax done in base 2

// Scratch (allocation-free rule: __device__ globals)
__device__ __nv_bfloat16 g_h  [MTOT * DMOD];
__device__ __nv_bfloat16 g_q  [MTOT * DMOD];  // [B,H,S,DK], pre-scaled by QSCALE
__device__ __nv_bfloat16 g_k  [MTOT * DMOD];  // [B,H,S,DK]
__device__ __half        g_v  [MTOT * DMOD];  // [B,H,S,DK] fp16 (PV mma is fp16)
__device__ __nv_bfloat16 g_att[MTOT * DMOD];  // [B,S,D]
__device__ __nv_bfloat16 g_wq [DMOD * DMOD];
__device__ __nv_bfloat16 g_wk [DMOD * DMOD];
__device__ __nv_bfloat16 g_wv [DMOD * DMOD];
__device__ __nv_bfloat16 g_wo [DMOD * DMOD];

// ---------------------------------------------------------------------------
// Helpers
// ---------------------------------------------------------------------------
__device__ __forceinline__ unsigned pack_bf2(float lo, float hi) {
    unsigned r;
    asm("cvt.rn.bf16x2.f32 %0, %1, %2;" : "=r"(r) : "f"(hi), "f"(lo));
    return r;
}
__device__ __forceinline__ unsigned pack_hf2(float lo, float hi) {
    unsigned r;
    asm("cvt.rn.f16x2.f32 %0, %1, %2;" : "=r"(r) : "f"(hi), "f"(lo));
    return r;
}
__device__ __forceinline__ unsigned hex2(unsigned x) {  // exp2 on f16x2: 1 MUFU / 2 vals
    unsigned d;
    asm("ex2.approx.f16x2 %0, %1;" : "=r"(d) : "r"(x));
    return d;
}
__device__ __forceinline__ uint32_t smaddr(const void* p) {
    return (uint32_t)__cvta_generic_to_shared(p);
}
__device__ __forceinline__ void cpa(uint32_t dst, const void* src) {
    asm volatile("cp.async.ca.shared.global [%0], [%1], 16;" :: "r"(dst), "l"(src));
}
__device__ __forceinline__ void cp_commit() { asm volatile("cp.async.commit_group;"); }
__device__ __forceinline__ void cp_wait0()  { asm volatile("cp.async.wait_group 0;"); }

__device__ __forceinline__ void ldmx4(unsigned& r0, unsigned& r1, unsigned& r2,
                                      unsigned& r3, uint32_t a) {
    asm volatile("ldmatrix.sync.aligned.m8n8.x4.shared.b16 {%0,%1,%2,%3},[%4];"
                 : "=r"(r0), "=r"(r1), "=r"(r2), "=r"(r3) : "r"(a));
}
__device__ __forceinline__ void ldmx4t(unsigned& r0, unsigned& r1, unsigned& r2,
                                       unsigned& r3, uint32_t a) {
    asm volatile("ldmatrix.sync.aligned.m8n8.x4.trans.shared.b16 {%0,%1,%2,%3},[%4];"
                 : "=r"(r0), "=r"(r1), "=r"(r2), "=r"(r3) : "r"(a));
}
__device__ __forceinline__ void ldmx2t(unsigned& r0, unsigned& r1, uint32_t a) {
    asm volatile("ldmatrix.sync.aligned.m8n8.x2.trans.shared.b16 {%0,%1},[%2];"
                 : "=r"(r0), "=r"(r1) : "r"(a));
}
__device__ __forceinline__ void mma16(float* c, unsigned a0, unsigned a1,
                                      unsigned a2, unsigned a3,
                                      unsigned b0, unsigned b1) {
    asm volatile(
        "mma.sync.aligned.m16n8k16.row.col.f32.bf16.bf16.f32 "
        "{%0,%1,%2,%3}, {%4,%5,%6,%7}, {%8,%9}, {%0,%1,%2,%3};"
        : "+f"(c[0]), "+f"(c[1]), "+f"(c[2]), "+f"(c[3])
        : "r"(a0), "r"(a1), "r"(a2), "r"(a3), "r"(b0), "r"(b1));
}
__device__ __forceinline__ void mma16h(float* c, unsigned a0, unsigned a1,
                                       unsigned a2, unsigned a3,
                                       unsigned b0, unsigned b1) {
    asm volatile(
        "mma.sync.aligned.m16n8k16.row.col.f32.f16.f16.f32 "
        "{%0,%1,%2,%3}, {%4,%5,%6,%7}, {%8,%9}, {%0,%1,%2,%3};"
        : "+f"(c[0]), "+f"(c[1]), "+f"(c[2]), "+f"(c[3])
        : "r"(a0), "r"(a1), "r"(a2), "r"(a3), "r"(b0), "r"(b1));
}

// ---------------------------------------------------------------------------
// Weight pre-conversion: fp32 -> bf16, all four matrices. 65536 thr x 4 elems.
// ---------------------------------------------------------------------------
__global__ void __launch_bounds__(256) convw(const float* __restrict__ wq,
                                             const float* __restrict__ wk,
                                             const float* __restrict__ wv,
                                             const float* __restrict__ wo) {
    int i = blockIdx.x * 256 + threadIdx.x;   // 0..65535
    float4 a;
    a = ((const float4*)wq)[i];
    *(uint2*)(g_wq + 4 * i) = make_uint2(pack_bf2(a.x, a.y), pack_bf2(a.z, a.w));
    a = ((const float4*)wk)[i];
    *(uint2*)(g_wk + 4 * i) = make_uint2(pack_bf2(a.x, a.y), pack_bf2(a.z, a.w));
    a = ((const float4*)wv)[i];
    *(uint2*)(g_wv + 4 * i) = make_uint2(pack_bf2(a.x, a.y), pack_bf2(a.z, a.w));
    a = ((const float4*)wo)[i];
    *(uint2*)(g_wo + 4 * i) = make_uint2(pack_bf2(a.x, a.y), pack_bf2(a.z, a.w));
}

// ---------------------------------------------------------------------------
// LayerNorm: one block per row (512 floats), 128 threads x float4, bf16 out
// ---------------------------------------------------------------------------
__global__ void __launch_bounds__(128) ln_kernel(const float* __restrict__ x,
                                                 const float* __restrict__ gamma,
                                                 const float* __restrict__ beta) {
    int row = blockIdx.x;
    int t = threadIdx.x;
    float4 v = ((const float4*)(x + (size_t)row * DMOD))[t];
    float s  = v.x + v.y + v.z + v.w;
    float sq = v.x * v.x + v.y * v.y + v.z * v.z + v.w * v.w;
#pragma unroll
    for (int o = 16; o; o >>= 1) {
        s  += __shfl_xor_sync(0xffffffffu, s,  o);
        sq += __shfl_xor_sync(0xffffffffu, sq, o);
    }
    __shared__ float ss[4], ssq[4];
    int w = t >> 5;
    if ((t & 31) == 0) { ss[w] = s; ssq[w] = sq; }
    __syncthreads();
    s  = ss[0] + ss[1] + ss[2] + ss[3];
    sq = ssq[0] + ssq[1] + ssq[2] + ssq[3];
    float mu   = s * (1.0f / 512.0f);
    float var  = sq * (1.0f / 512.0f) - mu * mu;
    float rstd = rsqrtf(var + 1e-5f);
    float4 g  = ((const float4*)gamma)[t];
    float4 bt = ((const float4*)beta)[t];
    float ox = (v.x - mu) * rstd * g.x + bt.x;
    float oy = (v.y - mu) * rstd * g.y + bt.y;
    float oz = (v.z - mu) * rstd * g.z + bt.z;
    float ow = (v.w - mu) * rstd * g.w + bt.w;
    uint2 st = make_uint2(pack_bf2(ox, oy), pack_bf2(oz, ow));
    *(uint2*)(g_h + (size_t)row * DMOD + 4 * t) = st;
}

// ---------------------------------------------------------------------------
// Projection GEMMs: C = h @ W^T for W in {Wq,Wk,Wv} (blockIdx.z).
// 4 warps x 32 rows (2 m-tiles) — each B fragment feeds 4 MMAs.
// cp.async double-buffered. BM=128, BN=64, BK=64, 128 threads.
// ---------------------------------------------------------------------------
__global__ void __launch_bounds__(128, 3) proj_mma() {
    extern __shared__ __align__(16) __nv_bfloat16 dsm[];
    __nv_bfloat16* As = dsm;                   // 2 x 128*PADW
    __nv_bfloat16* Ws = dsm + 2 * 128 * PADW;  // 2 x 64*PADW

    const __nv_bfloat16* W =
        (blockIdx.z == 0) ? g_wq : ((blockIdx.z == 1) ? g_wk : g_wv);

    int tid = threadIdx.x;
    int w = tid >> 5, lane = tid & 31;
    int g = lane >> 2, tig = lane & 3;
    int m0 = blockIdx.y << 7;
    int n0 = blockIdx.x << 6;
    int r0w = w << 5;   // 32 rows per warp

    uint32_t a_base = smaddr(As) + ((r0w + (lane & 15)) * PADW + ((lane >> 4) << 3)) * 2;
    uint32_t b_base = smaddr(Ws) + ((((lane >> 4) << 3) + (lane & 7)) * PADW
                                    + (((lane >> 3) & 1) << 3)) * 2;
    const uint32_t a_step = 128 * PADW * 2;
    const uint32_t b_step = 64 * PADW * 2;
    const uint32_t mt_step = 16 * PADW * 2;

    auto issue = [&](int kt, int buf) {
        uint32_t ad = smaddr(As + buf * 128 * PADW);
        uint32_t wd = smaddr(Ws + buf * 64 * PADW);
        int k0 = kt << 6;
        for (int i = tid; i < 1024; i += 128) {
            int r = i >> 3, c8 = (i & 7) << 3;
            cpa(ad + (r * PADW + c8) * 2, g_h + (size_t)(m0 + r) * DMOD + k0 + c8);
        }
        for (int i = tid; i < 512; i += 128) {
            int r = i >> 3, c8 = (i & 7) << 3;
            cpa(wd + (r * PADW + c8) * 2, W + (size_t)(n0 + r) * DMOD + k0 + c8);
        }
        cp_commit();
    };

    float acc[2][8][4];
#pragma unroll
    for (int mt = 0; mt < 2; mt++)
#pragma unroll
        for (int j = 0; j < 8; j++)
#pragma unroll
            for (int i = 0; i < 4; i++) acc[mt][j][i] = 0.f;

    issue(0, 0);
    cp_wait0();
    __syncthreads();

    for (int kt = 0; kt < 8; kt++) {
        int buf = kt & 1;
        if (kt + 1 < 8) issue(kt + 1, buf ^ 1);

        uint32_t ab = a_base + buf * a_step;
        uint32_t bb = b_base + buf * b_step;
#pragma unroll
        for (int ks = 0; ks < 4; ks++) {
            unsigned a[2][4];
#pragma unroll
            for (int mt = 0; mt < 2; mt++)
                ldmx4(a[mt][0], a[mt][1], a[mt][2], a[mt][3],
                      ab + mt * mt_step + (16 * ks) * 2);
#pragma unroll
            for (int jp = 0; jp < 4; jp++) {
                unsigned b0, b1, b2, b3;
                ldmx4(b0, b1, b2, b3, bb + ((16 * jp) * PADW + 16 * ks) * 2);
#pragma unroll
                for (int mt = 0; mt < 2; mt++) {
                    mma16(acc[mt][2 * jp],     a[mt][0], a[mt][1], a[mt][2], a[mt][3], b0, b1);
                    mma16(acc[mt][2 * jp + 1], a[mt][0], a[mt][1], a[mt][2], a[mt][3], b2, b3);
                }
            }
        }
        if (kt + 1 < 8) { cp_wait0(); __syncthreads(); }
    }

    int b = m0 >> 12;
    int head = blockIdx.x;
#pragma unroll
    for (int mt = 0; mt < 2; mt++) {
        int r1 = m0 + r0w + 16 * mt + g;
        int s1 = r1 & (SEQ - 1);
#pragma unroll
        for (int j = 0; j < 8; j++) {
            int col = 8 * j + 2 * tig;
            if (blockIdx.z == 2) {  // V -> fp16
                __half* Cb = g_v + (size_t)(b * NHEAD + head) * SEQ * DK;
                *(unsigned*)(Cb + (size_t)s1 * DK + col) =
                    pack_hf2(acc[mt][j][0], acc[mt][j][1]);
                *(unsigned*)(Cb + (size_t)(s1 + 8) * DK + col) =
                    pack_hf2(acc[mt][j][2], acc[mt][j][3]);
            } else {
                float scale = (blockIdx.z == 0) ? QSCALE : 1.0f;
                __nv_bfloat16* Cb = ((blockIdx.z == 0) ? g_q : g_k)
                                    + (size_t)(b * NHEAD + head) * SEQ * DK;
                *(unsigned*)(Cb + (size_t)s1 * DK + col) =
                    pack_bf2(acc[mt][j][0] * scale, acc[mt][j][1] * scale);
                *(unsigned*)(Cb + (size_t)(s1 + 8) * DK + col) =
                    pack_bf2(acc[mt][j][2] * scale, acc[mt][j][3] * scale);
            }
        }
    }
}

// ---------------------------------------------------------------------------
// Flash attention, unnormalized base-2 softmax, SOFTWARE-PIPELINED stages:
// for each 16-key group p: S(p) MMAs -> exp2(p) -> PV(p). Stages p are
// independent chains, so tensor (S of p+1) overlaps MUFU (exp of p) within
// one warp, and only one s-tile pair is live at a time (reg pressure down,
// 3 CTAs/SM). Row-sum l via ones-column of V. cp.async double-buffered K/V.
// Grid (SEQ/128, B*H), 128 threads (4 warps x 32 q-rows).
// ---------------------------------------------------------------------------
__global__ void __launch_bounds__(128, 3) attn_mma() {
    extern __shared__ __align__(16) __nv_bfloat16 dsm[];
    __nv_bfloat16* Qs = dsm;                          // 128*PADW
    __nv_bfloat16* Ks = dsm + 128 * PADW;             // 2 x 64*PADW
    __half*        Vs = (__half*)(Ks + 2 * 64 * PADW);// 2 x 64*PADW

    int tid = threadIdx.x;
    int w = tid >> 5, lane = tid & 31;
    int g = lane >> 2, tig = lane & 3;
    int q0 = blockIdx.x << 7;
    int bh = blockIdx.y;
    const __nv_bfloat16* Qb = g_q + (size_t)bh * SEQ * DK;
    const __nv_bfloat16* Kb = g_k + (size_t)bh * SEQ * DK;
    const __half*        Vb = g_v + (size_t)bh * SEQ * DK;
    int r0w = w << 5;   // 32 rows per warp

    auto issue_kv = [&](int t, int buf) {
        uint32_t kd = smaddr(Ks + buf * 64 * PADW);
        uint32_t vd = smaddr(Vs + buf * 64 * PADW);
        const __nv_bfloat16* ks = Kb + (size_t)(t << 6) * DK;
        const __half*        vs = Vb + (size_t)(t << 6) * DK;
        for (int i = tid; i < 512; i += 128) {
            int r = i >> 3, c8 = (i & 7) << 3;
            cpa(kd + (r * PADW + c8) * 2, ks + r * DK + c8);
            cpa(vd + (r * PADW + c8) * 2, vs + r * DK + c8);
        }
        cp_commit();
    };

    // Prologue: Q tile + KV tile 0
    {
        uint32_t qd = smaddr(Qs);
        for (int i = tid; i < 1024; i += 128) {
            int r = i >> 3, c8 = (i & 7) << 3;
            cpa(qd + (r * PADW + c8) * 2, Qb + (size_t)(q0 + r) * DK + c8);
        }
    }
    issue_kv(0, 0);

    // Ones-column init for BOTH V buffers (cols 64..71: [1,0,0,0,0,0,0,0]).
    // cp.async never touches these columns, so this persists across tiles.
    {
        int r = tid;  // 0..127 covers 2 bufs x 64 rows
        *(uint4*)(Vs + r * PADW + 64) = make_uint4(0x00003C00u, 0u, 0u, 0u);
    }

    cp_wait0();
    __syncthreads();

    // Q A-fragments for both m-tiles (persist in registers)
    unsigned qa[2][4][4];
#pragma unroll
    for (int mt = 0; mt < 2; mt++) {
        uint32_t qaddr = smaddr(Qs)
            + ((r0w + 16 * mt + (lane & 15)) * PADW + ((lane >> 4) << 3)) * 2;
#pragma unroll
        for (int ks = 0; ks < 4; ks++)
            ldmx4(qa[mt][ks][0], qa[mt][ks][1], qa[mt][ks][2], qa[mt][ks][3],
                  qaddr + (16 * ks) * 2);
    }

    uint32_t kb_base = smaddr(Ks) + ((((lane >> 4) << 3) + (lane & 7)) * PADW
                                     + (((lane >> 3) & 1) << 3)) * 2;
    uint32_t vb_base = smaddr(Vs) + (((((lane >> 3) & 1) << 3) + (lane & 7)) * PADW
                                     + ((lane >> 4) << 3)) * 2;
    uint32_t vl_base = smaddr(Vs) + ((lane & 15) * PADW + 64) * 2;  // ones-column
    const uint32_t kv_step = 64 * PADW * 2;

    float o[2][8][4];   // output accumulators (unnormalized)
    float ol[2][4];     // l accumulators (P @ ones-column)
#pragma unroll
    for (int mt = 0; mt < 2; mt++) {
#pragma unroll
        for (int j = 0; j < 8; j++)
#pragma unroll
            for (int i = 0; i < 4; i++) o[mt][j][i] = 0.f;
#pragma unroll
        for (int i = 0; i < 4; i++) ol[mt][i] = 0.f;
    }

    for (int t = 0; t < SEQ / 64; t++) {
        int buf = t & 1;
        if (t + 1 < SEQ / 64) issue_kv(t + 1, buf ^ 1);

        uint32_t kb = kb_base + buf * kv_step;
        uint32_t vb = vb_base + buf * kv_step;
        uint32_t vl = vl_base + buf * kv_step;

        // Pipelined stages over 16-key groups p: S(p) -> exp(p) -> PV(p).
#pragma unroll
        for (int p = 0; p < 4; p++) {
            // S n-tile pair: score columns (keys) 16p .. 16p+15
            float s0[2][4], s1[2][4];
#pragma unroll
            for (int mt = 0; mt < 2; mt++)
#pragma unroll
                for (int i = 0; i < 4; i++) { s0[mt][i] = 0.f; s1[mt][i] = 0.f; }
#pragma unroll
            for (int ks = 0; ks < 4; ks++) {
                unsigned b0, b1, b2, b3;
                ldmx4(b0, b1, b2, b3, kb + ((16 * p) * PADW + 16 * ks) * 2);
#pragma unroll
                for (int mt = 0; mt < 2; mt++) {
                    mma16(s0[mt], qa[mt][ks][0], qa[mt][ks][1],
                          qa[mt][ks][2], qa[mt][ks][3], b0, b1);
                    mma16(s1[mt], qa[mt][ks][0], qa[mt][ks][1],
                          qa[mt][ks][2], qa[mt][ks][3], b2, b3);
                }
            }

            // P = exp2(s): fp16 pairs double as PV A-fragments
            unsigned ea0[2], eb0[2], ea1[2], eb1[2];
#pragma unroll
            for (int mt = 0; mt < 2; mt++) {
                ea0[mt] = hex2(pack_hf2(s0[mt][0], s0[mt][1]));  // rows g,   keys 16p+2tig
                eb0[mt] = hex2(pack_hf2(s0[mt][2], s0[mt][3]));  // rows g+8
                ea1[mt] = hex2(pack_hf2(s1[mt][0], s1[mt][1]));  // keys 16p+8+2tig
                eb1[mt] = hex2(pack_hf2(s1[mt][2], s1[mt][3]));
            }

            // PV k-step p: O += P(:,16p:16p+16) @ [V|1](16p:16p+16, :)
#pragma unroll
            for (int jp = 0; jp < 4; jp++) {
                unsigned b0, b1, b2, b3;
                ldmx4t(b0, b1, b2, b3, vb + ((16 * p) * PADW + 16 * jp) * 2);
#pragma unroll
                for (int mt = 0; mt < 2; mt++) {
                    mma16h(o[mt][2 * jp],     ea0[mt], eb0[mt], ea1[mt], eb1[mt], b0, b1);
                    mma16h(o[mt][2 * jp + 1], ea0[mt], eb0[mt], ea1[mt], eb1[mt], b2, b3);
                }
            }
            unsigned lb0, lb1;
            ldmx2t(lb0, lb1, vl + (16 * p) * PADW * 2);
#pragma unroll
            for (int mt = 0; mt < 2; mt++)
                mma16h(ol[mt], ea0[mt], eb0[mt], ea1[mt], eb1[mt], lb0, lb1);
        }

        if (t + 1 < SEQ / 64) { cp_wait0(); __syncthreads(); }
    }

    // Normalize (l lives in tig==0 lanes: col 64 -> frag col 0), write bf16
    int b = bh >> 3, head = bh & 7;
    __nv_bfloat16* Ob = g_att + (size_t)b * SEQ * DMOD + head * DK;
#pragma unroll
    for (int mt = 0; mt < 2; mt++) {
        float lr1 = __shfl_sync(0xffffffffu, ol[mt][0], lane & ~3);
        float lr2 = __shfl_sync(0xffffffffu, ol[mt][2], lane & ~3);
        float inv1 = 1.0f / lr1, inv2 = 1.0f / lr2;
        int row1 = q0 + r0w + 16 * mt + g;
#pragma unroll
        for (int j = 0; j < 8; j++) {
            int col = 8 * j + 2 * tig;
            *(unsigned*)(Ob + (size_t)row1 * DMOD + col) =
                pack_bf2(o[mt][j][0] * inv1, o[mt][j][1] * inv1);
            *(unsigned*)(Ob + (size_t)(row1 + 8) * DMOD + col) =
                pack_bf2(o[mt][j][2] * inv2, o[mt][j][3] * inv2);
        }
    }
}

// ---------------------------------------------------------------------------
// Output GEMM: out = att @ Wo^T + b_o + residual(x). 4 warps x 32 rows,
// cp.async double-buffered.
// ---------------------------------------------------------------------------
__global__ void __launch_bounds__(128, 3) out_mma(const float* __restrict__ bias,
                                                  const float* __restrict__ xres,
                                                  float* __restrict__ out) {
    extern __shared__ __align__(16) __nv_bfloat16 dsm[];
    __nv_bfloat16* As = dsm;
    __nv_bfloat16* Ws = dsm + 2 * 128 * PADW;

    int tid = threadIdx.x;
    int w = tid >> 5, lane = tid & 31;
    int g = lane >> 2, tig = lane & 3;
    int m0 = blockIdx.y << 7;
    int n0 = blockIdx.x << 6;
    int r0w = w << 5;

    uint32_t a_base = smaddr(As) + ((r0w + (lane & 15)) * PADW + ((lane >> 4) << 3)) * 2;
    uint32_t b_base = smaddr(Ws) + ((((lane >> 4) << 3) + (lane & 7)) * PADW
                                    + (((lane >> 3) & 1) << 3)) * 2;
    const uint32_t a_step = 128 * PADW * 2;
    const uint32_t b_step = 64 * PADW * 2;
    const uint32_t mt_step = 16 * PADW * 2;

    auto issue = [&](int kt, int buf) {
        uint32_t ad = smaddr(As + buf * 128 * PADW);
        uint32_t wd = smaddr(Ws + buf * 64 * PADW);
        int k0 = kt << 6;
        for (int i = tid; i < 1024; i += 128) {
            int r = i >> 3, c8 = (i & 7) << 3;
            cpa(ad + (r * PADW + c8) * 2, g_att + (size_t)(m0 + r) * DMOD + k0 + c8);
        }
        for (int i = tid; i < 512; i += 128) {
            int r = i >> 3, c8 = (i & 7) << 3;
            cpa(wd + (r * PADW + c8) * 2, g_wo + (size_t)(n0 + r) * DMOD + k0 + c8);
        }
        cp_commit();
    };

    float acc[2][8][4];
#pragma unroll
    for (int mt = 0; mt < 2; mt++)
#pragma unroll
        for (int j = 0; j < 8; j++)
#pragma unroll
            for (int i = 0; i < 4; i++) acc[mt][j][i] = 0.f;

    issue(0, 0);
    cp_wait0();
    __syncthreads();

    for (int kt = 0; kt < 8; kt++) {
        int buf = kt & 1;
        if (kt + 1 < 8) issue(kt + 1, buf ^ 1);

        uint32_t ab = a_base + buf * a_step;
        uint32_t bb = b_base + buf * b_step;
#pragma unroll
        for (int ks = 0; ks < 4; ks++) {
            unsigned a[2][4];
#pragma unroll
            for (int mt = 0; mt < 2; mt++)
                ldmx4(a[mt][0], a[mt][1], a[mt][2], a[mt][3],
                      ab + mt * mt_step + (16 * ks) * 2);
#pragma unroll
            for (int jp = 0; jp < 4; jp++) {
                unsigned b0, b1, b2, b3;
                ldmx4(b0, b1, b2, b3, bb + ((16 * jp) * PADW + 16 * ks) * 2);
#pragma unroll
                for (int mt = 0; mt < 2; mt++) {
                    mma16(acc[mt][2 * jp],     a[mt][0], a[mt][1], a[mt][2], a[mt][3], b0, b1);
                    mma16(acc[mt][2 * jp + 1], a[mt][0], a[mt][1], a[mt][2], a[mt][3], b2, b3);
                }
            }
        }
        if (kt + 1 < 8) { cp_wait0(); __syncthreads(); }
    }

#pragma unroll
    for (int mt = 0; mt < 2; mt++) {
        int r1 = m0 + r0w + 16 * mt + g;
#pragma unroll
        for (int j = 0; j < 8; j++) {
            int col = n0 + 8 * j + 2 * tig;
            float2 bb = *(const float2*)(bias + col);
            float2 x1 = *(const float2*)(xres + (size_t)r1 * DMOD + col);
            float2 x2 = *(const float2*)(xres + (size_t)(r1 + 8) * DMOD + col);
            *(float2*)(out + (size_t)r1 * DMOD + col) =
                make_float2(acc[mt][j][0] + bb.x + x1.x, acc[mt][j][1] + bb.y + x1.y);
            *(float2*)(out + (size_t)(r1 + 8) * DMOD + col) =
                make_float2(acc[mt][j][2] + bb.x + x2.x, acc[mt][j][3] + bb.y + x2.y);
        }
    }
}

// ---------------------------------------------------------------------------
extern "C" void kernel_launch(void* const* d_in, const int* in_sizes, int n_in,
                              void* d_out, int out_size) {
    const float* x   = (const float*)d_in[0];
    const float* w_q = (const float*)d_in[1];
    const float* w_k = (const float*)d_in[2];
    const float* w_v = (const float*)d_in[3];
    const float* w_o = (const float*)d_in[4];
    const float* b_o = (const float*)d_in[5];
    const float* gam = (const float*)d_in[6];
    const float* bet = (const float*)d_in[7];
    float* out = (float*)d_out;

    const int smem_sz = (2 * 128 + 2 * 64) * PADW * 2;  // 55296 B (all 3 kernels)
    static int configured = 0;
    if (!configured) {
        cudaFuncSetAttribute(proj_mma, cudaFuncAttributeMaxDynamicSharedMemorySize, smem_sz);
        cudaFuncSetAttribute(attn_mma, cudaFuncAttributeMaxDynamicSharedMemorySize, smem_sz);
        cudaFuncSetAttribute(out_mma,  cudaFuncAttributeMaxDynamicSharedMemorySize, smem_sz);
        configured = 1;
    }

    convw<<<256, 256>>>(w_q, w_k, w_v, w_o);
    ln_kernel<<<MTOT, 128>>>(x, gam, bet);

    proj_mma<<<dim3(DMOD / 64, MTOT / 128, 3), 128, smem_sz>>>();

    attn_mma<<<dim3(SEQ / 128, 16), 128, smem_sz>>>();

    out_mma<<<dim3(DMOD / 64, MTOT / 128), 128, smem_sz>>>(b_o, x, out);
}